// round 7
// baseline (speedup 1.0000x reference)
#include <cuda_runtime.h>
#include <cuda_bf16.h>
#include <cstdint>

// ---------------------------------------------------------------------------
// cross_set_score, TF32 pipeline (v4: LDS.64 fragments via implicit K-permute):
//  K0: g_W1T = transpose(W1) tf32-rounded; zero completion counter
//  K1: H[tile,head] = x[tile] @ W1_head   (512-thr CTA, 128 rows x 4 heads)
//  K2: S = sum leakyrelu(A@B^T)           (256-thr CTA, A-half x B-half)
//      + last CTA applies W2 / nItem normalization and writes out
// K-slot remap (order-invariant sum): mma slot c -> col k0+2c, slot c+4 ->
// col k0+2c+1, identically for A and B => fragment pairs are SMEM-adjacent.
// ---------------------------------------------------------------------------

#define NSET  16
#define MITEM 256
#define DIN   128
#define NHEAD 8
#define DHEAD 64
#define NPAIR 136

#define XSTR  136     // 32-bit stride, ≡8 mod 32 -> conflict-free LDS.64
#define HSTR  72      // 32-bit stride, ≡8 mod 32 -> conflict-free LDS.64

#define SCORE_GRID (NPAIR * NHEAD * 4)

__device__ float g_H[NSET * NSET * NHEAD * MITEM * DHEAD];   // 134 MB scratch
__device__ float g_W1T[NHEAD * DHEAD * DIN];                 // [head][e][d], tf32 bits
__device__ float g_scratch[NPAIR * NHEAD * 4];               // 4 quadrant sums
__device__ int   g_count;                                    // score-CTA completion counter

// ---------------- PTX helpers ----------------
__device__ __forceinline__ uint32_t tf32_rna(float v) {
    uint32_t o;
    asm("cvt.rna.tf32.f32 %0, %1;" : "=r"(o) : "f"(v));
    return o;
}
__device__ __forceinline__ void mma_tf32(float* c, const uint32_t* a, const uint32_t* b) {
    asm volatile(
        "mma.sync.aligned.m16n8k8.row.col.f32.tf32.tf32.f32 "
        "{%0,%1,%2,%3}, {%4,%5,%6,%7}, {%8,%9}, {%0,%1,%2,%3};"
        : "+f"(c[0]), "+f"(c[1]), "+f"(c[2]), "+f"(c[3])
        : "r"(a[0]), "r"(a[1]), "r"(a[2]), "r"(a[3]), "r"(b[0]), "r"(b[1]));
}

// ============================================================================
// Kernel 0: transpose + tf32-round W1; reset counter.
// ============================================================================
__global__ void prep_w1(const float* __restrict__ W1)
{
    const int idx = blockIdx.x * 1024 + threadIdx.x;   // 65536 total
    if (idx == 0) g_count = 0;
    const int he  = idx >> 7;            // head*64 + e
    const int d   = idx & 127;
    g_W1T[idx] = __uint_as_float(tf32_rna(W1[d * (NHEAD * DHEAD) + he]));
}

// ============================================================================
// Kernel 1: projection. grid = 256 tiles * 2 row-halves * 2 head-groups.
// 512 threads, 16 warps (4m x 4n), warp tile 32x16. SMEM ~102KB -> 2 CTA/SM.
// ============================================================================
__global__ __launch_bounds__(512, 2)
void proj_kernel(const float* __restrict__ x)
{
    extern __shared__ uint32_t sm1[];
    uint32_t* xs  = sm1;                    // [128][XSTR]
    uint32_t* w1s = sm1 + 128 * XSTR;       // [64][XSTR]  (one head, e-major)

    const int bx   = blockIdx.x;
    const int tile = bx >> 2;
    const int rh   = (bx >> 1) & 1;
    const int hg   = bx & 1;
    const int tid  = threadIdx.x;
    const int wid  = tid >> 5;
    const int lane = tid & 31;
    const int r    = lane >> 2;
    const int c    = lane & 3;

    // ---- load x half-tile (fp32 -> tf32 bits): 128 x 128 ----
    {
        const float4* g = (const float4*)(x + ((size_t)tile * MITEM + rh * 128) * DIN);
        #pragma unroll
        for (int it = 0; it < 8; ++it) {
            int idx = tid + it * 512;
            float4 v = g[idx];
            int row = idx >> 5, cc = (idx & 31) << 2;
            uint4 w = { tf32_rna(v.x), tf32_rna(v.y), tf32_rna(v.z), tf32_rna(v.w) };
            *(uint4*)&xs[row * XSTR + cc] = w;
        }
    }
    // ---- stage W1 head slice: straight uint4 copy ----
    {
        const uint4* w1g = (const uint4*)(g_W1T + (size_t)(hg * 4) * DHEAD * DIN);
        #pragma unroll
        for (int it = 0; it < 4; ++it) {
            int idx = tid + it * 512;
            int e = idx >> 5, dq = idx & 31;
            *(uint4*)&w1s[e * XSTR + dq * 4] = w1g[idx];
        }
    }
    __syncthreads();

    const int wm = (wid & 3) * 32;
    const int wn = (wid >> 2) * 16;

    #pragma unroll 1
    for (int h = 0; h < 4; ++h) {
        const int head = hg * 4 + h;

        float acc[2][2][4];
        #pragma unroll
        for (int mt = 0; mt < 2; ++mt)
            #pragma unroll
            for (int nt = 0; nt < 2; ++nt)
                #pragma unroll
                for (int e = 0; e < 4; ++e) acc[mt][nt][e] = 0.f;

        #pragma unroll
        for (int ks = 0; ks < 16; ++ks) {
            const int k0 = ks * 8 + 2 * c;
            uint32_t af[2][4], bf[2][2];
            #pragma unroll
            for (int mt = 0; mt < 2; ++mt) {
                uint2 lo = *(const uint2*)&xs[(wm + mt * 16 + r) * XSTR + k0];
                uint2 hi = *(const uint2*)&xs[(wm + mt * 16 + r + 8) * XSTR + k0];
                af[mt][0] = lo.x; af[mt][2] = lo.y;
                af[mt][1] = hi.x; af[mt][3] = hi.y;
            }
            #pragma unroll
            for (int nt = 0; nt < 2; ++nt) {
                uint2 w = *(const uint2*)&w1s[(wn + nt * 8 + r) * XSTR + k0];
                bf[nt][0] = w.x; bf[nt][1] = w.y;
            }
            #pragma unroll
            for (int mt = 0; mt < 2; ++mt)
                #pragma unroll
                for (int nt = 0; nt < 2; ++nt)
                    mma_tf32(acc[mt][nt], af[mt], bf[nt]);
        }

        float* Hout = g_H + (size_t)(tile * NHEAD + head) * MITEM * DHEAD;
        #pragma unroll
        for (int mt = 0; mt < 2; ++mt)
            #pragma unroll
            for (int nt = 0; nt < 2; ++nt) {
                int row = rh * 128 + wm + mt * 16 + r;
                int col = wn + nt * 8 + c * 2;
                float2 lo = { __uint_as_float(tf32_rna(acc[mt][nt][0])),
                              __uint_as_float(tf32_rna(acc[mt][nt][1])) };
                float2 hi = { __uint_as_float(tf32_rna(acc[mt][nt][2])),
                              __uint_as_float(tf32_rna(acc[mt][nt][3])) };
                *(float2*)&Hout[row * DHEAD + col]       = lo;
                *(float2*)&Hout[(row + 8) * DHEAD + col] = hi;
            }

        if (h < 3) {
            __syncthreads();
            const uint4* w1gn = (const uint4*)(g_W1T + (size_t)(head + 1) * DHEAD * DIN);
            #pragma unroll
            for (int it = 0; it < 4; ++it) {
                int idx = tid + it * 512;
                int e = idx >> 5, dq = idx & 31;
                *(uint4*)&w1s[e * XSTR + dq * 4] = w1gn[idx];
            }
            __syncthreads();
        }
    }
}

// ============================================================================
// Kernel 2: score. grid = 136 pairs * 8 heads * 2 A-halves * 2 B-halves.
// 256 threads, 8 warps, warp tile 16x128. SMEM ~72KB -> 3 CTA/SM.
// Last CTA to finish performs the finalize (W2 + nItem normalization).
// ============================================================================
__global__ __launch_bounds__(256, 3)
void score_kernel(const float* __restrict__ nItem,
                  const float* __restrict__ W2,
                  float* __restrict__ out)
{
    extern __shared__ uint32_t sm2[];
    uint32_t* As   = sm2;                          // [128][HSTR]
    uint32_t* Bs   = sm2 + 128 * HSTR;             // [128][HSTR]
    float*    red  = (float*)(sm2 + 2 * 128 * HSTR);   // [8]
    int*      flag = (int*)(red + 8);

    const int bx   = blockIdx.x;
    const int pair = bx >> 5;
    const int head = (bx >> 2) & 7;
    const int ah   = (bx >> 1) & 1;
    const int bh   = bx & 1;
    const int tid  = threadIdx.x;
    const int wid  = tid >> 5;
    const int lane = tid & 31;
    const int r    = lane >> 2;
    const int c    = lane & 3;

    // pair -> (ii <= jj)
    int q = pair, jj = 0;
    while (q >= jj + 1) { q -= (jj + 1); ++jj; }
    const int ii = q;

    // load A half (128x64) and B half (128x64)
    {
        const uint4* gA = (const uint4*)(g_H + (size_t)((jj * NSET + ii) * NHEAD + head) * MITEM * DHEAD
                                         + (size_t)ah * 128 * DHEAD);
        const uint4* gB = (const uint4*)(g_H + (size_t)((ii * NSET + jj) * NHEAD + head) * MITEM * DHEAD
                                         + (size_t)bh * 128 * DHEAD);
        #pragma unroll
        for (int it = 0; it < 8; ++it) {
            int idx = tid + it * 256;
            uint4 va = gA[idx];
            uint4 vb = gB[idx];
            int row = idx >> 4, cc = (idx & 15) << 2;
            *(uint4*)&As[row * HSTR + cc] = va;
            *(uint4*)&Bs[row * HSTR + cc] = vb;
        }
    }
    __syncthreads();

    // warp tile: 16 rows x 128 cols
    const int wm = wid * 16;

    // resident A fragments: 8 k-steps x 4 regs = 32 regs
    uint32_t aF[8][4];
    #pragma unroll
    for (int ks = 0; ks < 8; ++ks) {
        uint2 lo = *(const uint2*)&As[(wm + r) * HSTR + ks * 8 + 2 * c];
        uint2 hi = *(const uint2*)&As[(wm + r + 8) * HSTR + ks * 8 + 2 * c];
        aF[ks][0] = lo.x; aF[ks][2] = lo.y;
        aF[ks][1] = hi.x; aF[ks][3] = hi.y;
    }

    float sum = 0.f;
    #pragma unroll
    for (int nt = 0; nt < 16; ++nt) {
        uint32_t bF[8][2];
        #pragma unroll
        for (int ks = 0; ks < 8; ++ks) {
            uint2 w = *(const uint2*)&Bs[(nt * 8 + r) * HSTR + ks * 8 + 2 * c];
            bF[ks][0] = w.x; bF[ks][1] = w.y;
        }
        float cc4[4] = {0.f, 0.f, 0.f, 0.f};
        #pragma unroll
        for (int ks = 0; ks < 8; ++ks)
            mma_tf32(cc4, aF[ks], bF[ks]);
        #pragma unroll
        for (int e = 0; e < 4; ++e) {
            float v = cc4[e];
            sum += (v > 0.f) ? v : 0.3f * v;     // LeakyReLU(0.3)
        }
    }

    // CTA reduce -> deterministic quadrant slot
    #pragma unroll
    for (int off = 16; off; off >>= 1)
        sum += __shfl_xor_sync(0xffffffffu, sum, off);
    if (lane == 0) red[wid] = sum;
    __syncthreads();
    if (tid == 0) {
        float t = 0.f;
        #pragma unroll
        for (int w = 0; w < 8; ++w) t += red[w];
        g_scratch[((pair * NHEAD + head) * 2 + ah) * 2 + bh] = t;
        __threadfence();
        int done = atomicAdd(&g_count, 1);
        *flag = (done == SCORE_GRID - 1);
    }
    __syncthreads();

    // ---- last CTA: finalize ----
    if (*flag) {
        __threadfence();   // order scratch reads after the counter observation
        const int t = tid;             // t = j*16 + i
        const int j = t >> 4, i = t & 15;
        const int a = (j > i) ? j : i;
        const int b = (j > i) ? i : j;
        const int p = a * (a + 1) / 2 + b;
        float s = 0.f;
        #pragma unroll
        for (int hh = 0; hh < NHEAD; ++hh) {
            const float* qd = &g_scratch[(p * NHEAD + hh) * 4];
            s += (qd[0] + qd[1] + qd[2] + qd[3]) * W2[hh];
        }
        out[t] = s / (8.0f * nItem[i] * nItem[j]);   // 8 = sqrt(D=64)
    }
}

// ---------------- entry point ----------------
#define SMEM_K1 ((128 * XSTR + DHEAD * XSTR) * 4)            // 104448
#define SMEM_K2 ((2 * 128 * HSTR) * 4 + 64)                  // 73792

extern "C" void kernel_launch(void* const* d_in, const int* in_sizes, int n_in,
                              void* d_out, int out_size)
{
    const float* x = nullptr;
    const float* nItem = nullptr;
    const float* W1 = nullptr;
    const float* W2 = nullptr;
    for (int k = 0; k < n_in; ++k) {
        switch (in_sizes[k]) {
            case NSET * NSET * MITEM * DIN: x     = (const float*)d_in[k]; break;
            case NSET:                      nItem = (const float*)d_in[k]; break;
            case DIN * NHEAD * DHEAD:       W1    = (const float*)d_in[k]; break;
            case NHEAD:                     W2    = (const float*)d_in[k]; break;
        }
    }

    static bool attr_done = false;
    if (!attr_done) {
        cudaFuncSetAttribute(proj_kernel,
                             cudaFuncAttributeMaxDynamicSharedMemorySize, SMEM_K1);
        cudaFuncSetAttribute(score_kernel,
                             cudaFuncAttributeMaxDynamicSharedMemorySize, SMEM_K2);
        attr_done = true;
    }

    prep_w1<<<64, 1024>>>(W1);
    proj_kernel<<<NSET * NSET * 2 * 2, 512, SMEM_K1>>>(x);
    score_kernel<<<SCORE_GRID, 256, SMEM_K2>>>(nItem, W2, (float*)d_out);
}

// round 9
// speedup vs baseline: 1.2811x; 1.2811x over previous
#include <cuda_runtime.h>
#include <cuda_bf16.h>
#include <cstdint>

// ---------------------------------------------------------------------------
// cross_set_score (v6): register-resident A, gmem-direct A feeds, minimal LDS.
//  K0: g_W1T = transpose(W1) tf32-rounded; zero completion counter
//  K1: proj: CTA = 128 x-rows (resident in regs) x all 8 heads; W1 via SMEM
//  K2: score: warp tile 32x128, A resident from gmem, B-half in SMEM;
//      bF shared across 2 m-tiles; last CTA finalizes output
// K-slot permute (sum-invariant): mma slot c -> col k0+2c, slot c+4 ->
// col k0+2c+1, same permutation for A and B  =>  8B-contiguous fragments.
// ---------------------------------------------------------------------------

#define NSET  16
#define MITEM 256
#define DIN   128
#define NHEAD 8
#define DHEAD 64
#define NPAIR 136

#define W1STR 136      // proj W1 smem stride (words), ==8 mod 32: conflict-free LDS.64
#define BSTR  72       // score B smem stride (words), ==8 mod 32: conflict-free LDS.64

#define SCORE_GRID (NPAIR * NHEAD * 2)

__device__ float g_H[NSET * NSET * NHEAD * MITEM * DHEAD];   // 134 MB scratch
__device__ float g_W1T[NHEAD * DHEAD * DIN];                 // [head][e][d], tf32 bits
__device__ float g_scratch[NPAIR * NHEAD * 2];               // 2 B-halves per (pair,head)
__device__ int   g_count;

// ---------------- PTX helpers ----------------
__device__ __forceinline__ uint32_t tf32_rna(float v) {
    uint32_t o;
    asm("cvt.rna.tf32.f32 %0, %1;" : "=r"(o) : "f"(v));
    return o;
}
__device__ __forceinline__ void mma_tf32(float* c, const uint32_t* a, const uint32_t* b) {
    asm volatile(
        "mma.sync.aligned.m16n8k8.row.col.f32.tf32.tf32.f32 "
        "{%0,%1,%2,%3}, {%4,%5,%6,%7}, {%8,%9}, {%0,%1,%2,%3};"
        : "+f"(c[0]), "+f"(c[1]), "+f"(c[2]), "+f"(c[3])
        : "r"(a[0]), "r"(a[1]), "r"(a[2]), "r"(a[3]), "r"(b[0]), "r"(b[1]));
}

// ============================================================================
// Kernel 0: transpose + tf32-round W1; reset completion counter.
// ============================================================================
__global__ void prep_w1(const float* __restrict__ W1)
{
    const int idx = blockIdx.x * 1024 + threadIdx.x;   // 65536 total
    if (idx == 0) g_count = 0;
    const int he  = idx >> 7;            // head*64 + e
    const int d   = idx & 127;
    g_W1T[idx] = __uint_as_float(tf32_rna(W1[d * (NHEAD * DHEAD) + he]));
}

// ============================================================================
// Kernel 1: projection. grid = 256 tiles * 2 row-halves = 512 CTAs, 256 thr.
// Warp owns 16 x-rows, resident across ALL 8 heads (64 regs of tf32 A).
// Per head: stage W1 slice (32KB) to SMEM, 8 n-tiles x 16 k-steps.
// ============================================================================
__global__ __launch_bounds__(256, 2)
void proj_kernel(const float* __restrict__ x)
{
    extern __shared__ uint32_t w1s[];    // [64][W1STR]

    const int bx   = blockIdx.x;
    const int tile = bx >> 1;
    const int rh   = bx & 1;
    const int tid  = threadIdx.x;
    const int wid  = tid >> 5;
    const int lane = tid & 31;
    const int r    = lane >> 2;
    const int c    = lane & 3;

    // ---- load A resident: 16 rows x 128 K per warp, tf32-rounded ----
    uint32_t aF[16][4];
    {
        const float* xr0 = x + (size_t)(tile * MITEM + rh * 128 + wid * 16 + r) * DIN;
        const float* xr8 = xr0 + 8 * DIN;
        #pragma unroll
        for (int ks = 0; ks < 16; ++ks) {
            float2 lo = *(const float2*)(xr0 + ks * 8 + 2 * c);
            float2 hi = *(const float2*)(xr8 + ks * 8 + 2 * c);
            aF[ks][0] = tf32_rna(lo.x); aF[ks][2] = tf32_rna(lo.y);
            aF[ks][1] = tf32_rna(hi.x); aF[ks][3] = tf32_rna(hi.y);
        }
    }

    #pragma unroll 1
    for (int h = 0; h < NHEAD; ++h) {
        __syncthreads();   // previous head's w1s reads complete
        // stage W1 head slice: 2048 uint4, straight copy
        {
            const uint4* w1g = (const uint4*)(g_W1T + (size_t)h * DHEAD * DIN);
            #pragma unroll
            for (int it = 0; it < 8; ++it) {
                int idx = tid + it * 256;
                int e = idx >> 5, dq = idx & 31;
                *(uint4*)&w1s[e * W1STR + dq * 4] = w1g[idx];
            }
        }
        __syncthreads();

        float* Hout = g_H + ((size_t)(tile * NHEAD + h) * MITEM
                             + rh * 128 + wid * 16) * DHEAD;

        #pragma unroll
        for (int ntp = 0; ntp < 4; ++ntp) {
            const int n0 = ntp * 16;
            const int n1 = n0 + 8;
            float acc0[4] = {0.f, 0.f, 0.f, 0.f};
            float acc1[4] = {0.f, 0.f, 0.f, 0.f};
            #pragma unroll
            for (int ks = 0; ks < 16; ++ks) {
                uint2 b0 = *(const uint2*)&w1s[(n0 + r) * W1STR + ks * 8 + 2 * c];
                uint2 b1 = *(const uint2*)&w1s[(n1 + r) * W1STR + ks * 8 + 2 * c];
                mma_tf32(acc0, aF[ks], (const uint32_t*)&b0);
                mma_tf32(acc1, aF[ks], (const uint32_t*)&b1);
            }
            // store tf32-rounded: rows r / r+8, cols n0+2c / n1+2c
            float2 v;
            v.x = __uint_as_float(tf32_rna(acc0[0]));
            v.y = __uint_as_float(tf32_rna(acc0[1]));
            *(float2*)&Hout[r * DHEAD + n0 + 2 * c] = v;
            v.x = __uint_as_float(tf32_rna(acc0[2]));
            v.y = __uint_as_float(tf32_rna(acc0[3]));
            *(float2*)&Hout[(r + 8) * DHEAD + n0 + 2 * c] = v;
            v.x = __uint_as_float(tf32_rna(acc1[0]));
            v.y = __uint_as_float(tf32_rna(acc1[1]));
            *(float2*)&Hout[r * DHEAD + n1 + 2 * c] = v;
            v.x = __uint_as_float(tf32_rna(acc1[2]));
            v.y = __uint_as_float(tf32_rna(acc1[3]));
            *(float2*)&Hout[(r + 8) * DHEAD + n1 + 2 * c] = v;
        }
    }
}

// ============================================================================
// Kernel 2: score. grid = 136 pairs * 8 heads * 2 B-halves = 2176, 256 thr.
// Warp tile 32x128: A (2 m-tiles) resident from gmem (no cvt, H is tf32),
// B-half staged in SMEM; each bF feeds both m-tiles. Fused LeakyReLU+reduce.
// Last CTA to finish applies W2 + nItem normalization and writes out.
// ============================================================================
__global__ __launch_bounds__(256, 2)
void score_kernel(const float* __restrict__ nItem,
                  const float* __restrict__ W2,
                  float* __restrict__ out)
{
    extern __shared__ uint32_t sm2[];
    uint32_t* Bs   = sm2;                              // [128][BSTR]
    float*    red  = (float*)(sm2 + 128 * BSTR);       // [8]
    int*      flag = (int*)(red + 8);

    const int bx   = blockIdx.x;
    const int pair = bx >> 4;
    const int head = (bx >> 1) & 7;
    const int bh   = bx & 1;
    const int tid  = threadIdx.x;
    const int wid  = tid >> 5;
    const int lane = tid & 31;
    const int r    = lane >> 2;
    const int c    = lane & 3;

    // pair -> (ii <= jj)
    int q = pair, jj = 0;
    while (q >= jj + 1) { q -= (jj + 1); ++jj; }
    const int ii = q;

    const float* HA = g_H + (size_t)((jj * NSET + ii) * NHEAD + head) * MITEM * DHEAD;
    const float* HB = g_H + (size_t)((ii * NSET + jj) * NHEAD + head) * MITEM * DHEAD
                      + (size_t)bh * 128 * DHEAD;

    // ---- A resident: 32 rows (2 m-tiles) x 64 K per warp, from gmem ----
    uint32_t aF[2][8][4];
    {
        const int wm = wid * 32;
        #pragma unroll
        for (int mt = 0; mt < 2; ++mt) {
            const float* a0 = HA + (size_t)(wm + mt * 16 + r) * DHEAD;
            const float* a8 = a0 + 8 * DHEAD;
            #pragma unroll
            for (int ks = 0; ks < 8; ++ks) {
                float2 lo = *(const float2*)(a0 + ks * 8 + 2 * c);
                float2 hi = *(const float2*)(a8 + ks * 8 + 2 * c);
                aF[mt][ks][0] = __float_as_uint(lo.x);
                aF[mt][ks][2] = __float_as_uint(lo.y);
                aF[mt][ks][1] = __float_as_uint(hi.x);
                aF[mt][ks][3] = __float_as_uint(hi.y);
            }
        }
    }

    // ---- stage B half: 2048 uint4 straight copy ----
    {
        const uint4* gB = (const uint4*)HB;
        #pragma unroll
        for (int it = 0; it < 8; ++it) {
            int idx = tid + it * 256;
            uint4 v = gB[idx];
            int row = idx >> 4, cq = idx & 15;
            *(uint4*)&Bs[row * BSTR + cq * 4] = v;
        }
    }
    __syncthreads();

    // ---- mainloop: 16 n-tiles, bF shared across both m-tiles ----
    float sum = 0.f;
    #pragma unroll 1
    for (int nt = 0; nt < 16; ++nt) {
        float acc0[4] = {0.f, 0.f, 0.f, 0.f};
        float acc1[4] = {0.f, 0.f, 0.f, 0.f};
        #pragma unroll
        for (int ks = 0; ks < 8; ++ks) {
            uint2 b = *(const uint2*)&Bs[(nt * 8 + r) * BSTR + ks * 8 + 2 * c];
            mma_tf32(acc0, aF[0][ks], (const uint32_t*)&b);
            mma_tf32(acc1, aF[1][ks], (const uint32_t*)&b);
        }
        #pragma unroll
        for (int e = 0; e < 4; ++e) {
            float v0 = acc0[e], v1 = acc1[e];
            sum += (v0 > 0.f) ? v0 : 0.3f * v0;
            sum += (v1 > 0.f) ? v1 : 0.3f * v1;
        }
    }

    // ---- CTA reduce ----
    #pragma unroll
    for (int off = 16; off; off >>= 1)
        sum += __shfl_xor_sync(0xffffffffu, sum, off);
    if (lane == 0) red[wid] = sum;
    __syncthreads();
    if (tid == 0) {
        float t = 0.f;
        #pragma unroll
        for (int w = 0; w < 8; ++w) t += red[w];
        g_scratch[(pair * NHEAD + head) * 2 + bh] = t;
        __threadfence();
        int done = atomicAdd(&g_count, 1);
        *flag = (done == SCORE_GRID - 1);
    }
    __syncthreads();

    // ---- last CTA: finalize ----
    if (*flag) {
        __threadfence();
        const int t = tid;             // t = j*16 + i
        const int j = t >> 4, i = t & 15;
        const int a = (j > i) ? j : i;
        const int b = (j > i) ? i : j;
        const int p = a * (a + 1) / 2 + b;
        float s = 0.f;
        #pragma unroll
        for (int hh = 0; hh < NHEAD; ++hh) {
            float sh = g_scratch[(p * NHEAD + hh) * 2]
                     + g_scratch[(p * NHEAD + hh) * 2 + 1];
            s += sh * W2[hh];
        }
        out[t] = s / (8.0f * nItem[i] * nItem[j]);   // 8 = sqrt(D=64)
    }
}

// ---------------- entry point ----------------
#define SMEM_K1 (DHEAD * W1STR * 4)              // 34816
#define SMEM_K2 (128 * BSTR * 4 + 64)            // 36928

extern "C" void kernel_launch(void* const* d_in, const int* in_sizes, int n_in,
                              void* d_out, int out_size)
{
    const float* x = nullptr;
    const float* nItem = nullptr;
    const float* W1 = nullptr;
    const float* W2 = nullptr;
    for (int k = 0; k < n_in; ++k) {
        switch (in_sizes[k]) {
            case NSET * NSET * MITEM * DIN: x     = (const float*)d_in[k]; break;
            case NSET:                      nItem = (const float*)d_in[k]; break;
            case DIN * NHEAD * DHEAD:       W1    = (const float*)d_in[k]; break;
            case NHEAD:                     W2    = (const float*)d_in[k]; break;
        }
    }

    prep_w1<<<64, 1024>>>(W1);
    proj_kernel<<<NSET * NSET * 2, 256, SMEM_K1>>>(x);
    score_kernel<<<SCORE_GRID, 256, SMEM_K2>>>(nItem, W2, (float*)d_out);
}

// round 11
// speedup vs baseline: 1.4173x; 1.1063x over previous
#include <cuda_runtime.h>
#include <cuda_bf16.h>
#include <cstdint>

// ---------------------------------------------------------------------------
// cross_set_score (v7b): v7 + restored MaxDynamicSharedMemorySize attributes.
//  K0: g_W1T = transpose(W1) tf32-rounded; zero completion counter
//  K1: proj: CTA = 128 x-rows (reg-resident) x 8 heads; W1 double-buffered
//  K2: score: CTA = (pair, head): A reg-resident from gmem, full B in SMEM
//      (512 mma/CTA); fused LeakyReLU+reduce; last CTA finalizes output
// ---------------------------------------------------------------------------

#define NSET  16
#define MITEM 256
#define DIN   128
#define NHEAD 8
#define DHEAD 64
#define NPAIR 136

#define W1STR 136      // words; ==8 mod 32 -> conflict-free LDS.64
#define BSTR  72       // words; ==8 mod 32 -> conflict-free LDS.64

#define SCORE_GRID (NPAIR * NHEAD)

__device__ float g_H[NSET * NSET * NHEAD * MITEM * DHEAD];   // 134 MB scratch
__device__ float g_W1T[NHEAD * DHEAD * DIN];                 // [head][e][d], tf32 bits
__device__ float g_scratch[NPAIR * NHEAD];
__device__ int   g_count;

// ---------------- PTX helpers ----------------
__device__ __forceinline__ uint32_t tf32_rna(float v) {
    uint32_t o;
    asm("cvt.rna.tf32.f32 %0, %1;" : "=r"(o) : "f"(v));
    return o;
}
__device__ __forceinline__ void mma_tf32(float* c, const uint32_t* a, const uint32_t* b) {
    asm volatile(
        "mma.sync.aligned.m16n8k8.row.col.f32.tf32.tf32.f32 "
        "{%0,%1,%2,%3}, {%4,%5,%6,%7}, {%8,%9}, {%0,%1,%2,%3};"
        : "+f"(c[0]), "+f"(c[1]), "+f"(c[2]), "+f"(c[3])
        : "r"(a[0]), "r"(a[1]), "r"(a[2]), "r"(a[3]), "r"(b[0]), "r"(b[1]));
}
__device__ __forceinline__ void cp_async16(uint32_t smem_addr, const void* gptr) {
    asm volatile("cp.async.cg.shared.global [%0], [%1], 16;"
                 :: "r"(smem_addr), "l"(gptr) : "memory");
}
__device__ __forceinline__ void cp_commit() {
    asm volatile("cp.async.commit_group;" ::: "memory");
}
__device__ __forceinline__ void cp_wait0() {
    asm volatile("cp.async.wait_group 0;" ::: "memory");
}
__device__ __forceinline__ uint32_t smem_u32(const void* p) {
    return (uint32_t)__cvta_generic_to_shared(p);
}

// ============================================================================
// Kernel 0: transpose + tf32-round W1; reset completion counter.
// ============================================================================
__global__ void prep_w1(const float* __restrict__ W1)
{
    const int idx = blockIdx.x * 1024 + threadIdx.x;   // 65536 total
    if (idx == 0) g_count = 0;
    const int he  = idx >> 7;            // head*64 + e
    const int d   = idx & 127;
    g_W1T[idx] = __uint_as_float(tf32_rna(W1[d * (NHEAD * DHEAD) + he]));
}

// ============================================================================
// Kernel 1: projection. grid = 512 CTAs (256 tiles x 2 halves), 256 thr.
// Warp owns 16 x-rows resident across all 8 heads. W1 double-buffered
// via cp.async: next head streams in while current head computes.
// ============================================================================
__global__ __launch_bounds__(256, 2)
void proj_kernel(const float* __restrict__ x)
{
    extern __shared__ uint32_t w1s[];    // 2 slots of [64][W1STR]

    const int bx   = blockIdx.x;
    const int tile = bx >> 1;
    const int rh   = bx & 1;
    const int tid  = threadIdx.x;
    const int wid  = tid >> 5;
    const int lane = tid & 31;
    const int r    = lane >> 2;
    const int c    = lane & 3;

    const uint32_t slot_bytes = DHEAD * W1STR * 4;
    const uint32_t w1s_base   = smem_u32(w1s);

    // issue cp.async for head h into slot s (8 uint4 chunks per thread)
    auto stage_head = [&](int h, int s) {
        const char* src = (const char*)(g_W1T + (size_t)h * DHEAD * DIN);
        const uint32_t dstb = w1s_base + s * slot_bytes;
        #pragma unroll
        for (int it = 0; it < 8; ++it) {
            int idx = tid + it * 256;
            int e = idx >> 5, dq = idx & 31;
            cp_async16(dstb + (e * W1STR + dq * 4) * 4, src + idx * 16);
        }
        cp_commit();
    };

    // ---- kick off head 0 staging, then load A resident (overlaps) ----
    stage_head(0, 0);

    uint32_t aF[16][4];
    {
        const float* xr0 = x + (size_t)(tile * MITEM + rh * 128 + wid * 16 + r) * DIN;
        const float* xr8 = xr0 + 8 * DIN;
        #pragma unroll
        for (int ks = 0; ks < 16; ++ks) {
            float2 lo = *(const float2*)(xr0 + ks * 8 + 2 * c);
            float2 hi = *(const float2*)(xr8 + ks * 8 + 2 * c);
            aF[ks][0] = tf32_rna(lo.x); aF[ks][2] = tf32_rna(lo.y);
            aF[ks][1] = tf32_rna(hi.x); aF[ks][3] = tf32_rna(hi.y);
        }
    }

    cp_wait0();
    __syncthreads();

    #pragma unroll 1
    for (int h = 0; h < NHEAD; ++h) {
        const int s = h & 1;
        if (h < NHEAD - 1) stage_head(h + 1, s ^ 1);   // prefetch next head

        const uint32_t* w1c = w1s + s * (DHEAD * W1STR);
        float* Hout = g_H + ((size_t)(tile * NHEAD + h) * MITEM
                             + rh * 128 + wid * 16) * DHEAD;

        #pragma unroll
        for (int ntp = 0; ntp < 4; ++ntp) {
            const int n0 = ntp * 16;
            const int n1 = n0 + 8;
            float acc0[4] = {0.f, 0.f, 0.f, 0.f};
            float acc1[4] = {0.f, 0.f, 0.f, 0.f};
            #pragma unroll
            for (int ks = 0; ks < 16; ++ks) {
                uint2 b0 = *(const uint2*)&w1c[(n0 + r) * W1STR + ks * 8 + 2 * c];
                uint2 b1 = *(const uint2*)&w1c[(n1 + r) * W1STR + ks * 8 + 2 * c];
                mma_tf32(acc0, aF[ks], (const uint32_t*)&b0);
                mma_tf32(acc1, aF[ks], (const uint32_t*)&b1);
            }
            float2 v;
            v.x = __uint_as_float(tf32_rna(acc0[0]));
            v.y = __uint_as_float(tf32_rna(acc0[1]));
            *(float2*)&Hout[r * DHEAD + n0 + 2 * c] = v;
            v.x = __uint_as_float(tf32_rna(acc0[2]));
            v.y = __uint_as_float(tf32_rna(acc0[3]));
            *(float2*)&Hout[(r + 8) * DHEAD + n0 + 2 * c] = v;
            v.x = __uint_as_float(tf32_rna(acc1[0]));
            v.y = __uint_as_float(tf32_rna(acc1[1]));
            *(float2*)&Hout[r * DHEAD + n1 + 2 * c] = v;
            v.x = __uint_as_float(tf32_rna(acc1[2]));
            v.y = __uint_as_float(tf32_rna(acc1[3]));
            *(float2*)&Hout[(r + 8) * DHEAD + n1 + 2 * c] = v;
        }

        if (h < NHEAD - 1) {
            cp_wait0();
            __syncthreads();   // next slot filled; current slot free for h+2
        }
    }
}

// ============================================================================
// Kernel 2: score. grid = 136 pairs * 8 heads = 1088 CTAs, 256 threads.
// Warp tile 32x256: A (2 m-tiles) resident from gmem, FULL B in SMEM via
// cp.async. 512 mma/CTA. Last CTA finalizes output.
// ============================================================================
__global__ __launch_bounds__(256, 2)
void score_kernel(const float* __restrict__ nItem,
                  const float* __restrict__ W2,
                  float* __restrict__ out)
{
    extern __shared__ uint32_t sm2[];
    uint32_t* Bs   = sm2;                              // [256][BSTR]
    float*    red  = (float*)(sm2 + 256 * BSTR);       // [8]
    int*      flag = (int*)(red + 8);

    const int bx   = blockIdx.x;
    const int pair = bx >> 3;
    const int head = bx & 7;
    const int tid  = threadIdx.x;
    const int wid  = tid >> 5;
    const int lane = tid & 31;
    const int r    = lane >> 2;
    const int c    = lane & 3;

    // pair -> (ii <= jj)
    int q = pair, jj = 0;
    while (q >= jj + 1) { q -= (jj + 1); ++jj; }
    const int ii = q;

    const float* HA = g_H + (size_t)((jj * NSET + ii) * NHEAD + head) * MITEM * DHEAD;
    const float* HB = g_H + (size_t)((ii * NSET + jj) * NHEAD + head) * MITEM * DHEAD;

    // ---- kick off B staging via cp.async (4096 uint4), then load A ----
    {
        const uint32_t bs_base = smem_u32(Bs);
        const char* src = (const char*)HB;
        #pragma unroll
        for (int it = 0; it < 16; ++it) {
            int idx = tid + it * 256;
            int row = idx >> 4, cq = idx & 15;
            cp_async16(bs_base + (row * BSTR + cq * 4) * 4, src + idx * 16);
        }
        cp_commit();
    }

    // A resident: 32 rows (2 m-tiles) x 64 K per warp, from gmem (tf32 bits)
    uint32_t aF[2][8][4];
    {
        const int wm = wid * 32;
        #pragma unroll
        for (int mt = 0; mt < 2; ++mt) {
            const float* a0 = HA + (size_t)(wm + mt * 16 + r) * DHEAD;
            const float* a8 = a0 + 8 * DHEAD;
            #pragma unroll
            for (int ks = 0; ks < 8; ++ks) {
                float2 lo = *(const float2*)(a0 + ks * 8 + 2 * c);
                float2 hi = *(const float2*)(a8 + ks * 8 + 2 * c);
                aF[mt][ks][0] = __float_as_uint(lo.x);
                aF[mt][ks][2] = __float_as_uint(lo.y);
                aF[mt][ks][1] = __float_as_uint(hi.x);
                aF[mt][ks][3] = __float_as_uint(hi.y);
            }
        }
    }

    cp_wait0();
    __syncthreads();

    // ---- mainloop: 32 n-tiles, bF shared across both m-tiles ----
    float sum = 0.f;
    #pragma unroll 1
    for (int nt = 0; nt < 32; ++nt) {
        float acc0[4] = {0.f, 0.f, 0.f, 0.f};
        float acc1[4] = {0.f, 0.f, 0.f, 0.f};
        #pragma unroll
        for (int ks = 0; ks < 8; ++ks) {
            uint2 b = *(const uint2*)&Bs[(nt * 8 + r) * BSTR + ks * 8 + 2 * c];
            mma_tf32(acc0, aF[0][ks], (const uint32_t*)&b);
            mma_tf32(acc1, aF[1][ks], (const uint32_t*)&b);
        }
        #pragma unroll
        for (int e = 0; e < 4; ++e) {
            float v0 = acc0[e], v1 = acc1[e];
            sum += (v0 > 0.f) ? v0 : 0.3f * v0;
            sum += (v1 > 0.f) ? v1 : 0.3f * v1;
        }
    }

    // ---- CTA reduce ----
    #pragma unroll
    for (int off = 16; off; off >>= 1)
        sum += __shfl_xor_sync(0xffffffffu, sum, off);
    if (lane == 0) red[wid] = sum;
    __syncthreads();
    if (tid == 0) {
        float t = 0.f;
        #pragma unroll
        for (int w = 0; w < 8; ++w) t += red[w];
        g_scratch[pair * NHEAD + head] = t;
        __threadfence();
        int done = atomicAdd(&g_count, 1);
        *flag = (done == SCORE_GRID - 1);
    }
    __syncthreads();

    // ---- last CTA: finalize ----
    if (*flag) {
        __threadfence();
        const int t = tid;             // t = j*16 + i
        const int j = t >> 4, i = t & 15;
        const int a = (j > i) ? j : i;
        const int b = (j > i) ? i : j;
        const int p = a * (a + 1) / 2 + b;
        float s = 0.f;
        #pragma unroll
        for (int hh = 0; hh < NHEAD; ++hh)
            s += g_scratch[p * NHEAD + hh] * W2[hh];
        out[t] = s / (8.0f * nItem[i] * nItem[j]);   // 8 = sqrt(D=64)
    }
}

// ---------------- entry point ----------------
#define SMEM_K1 (2 * DHEAD * W1STR * 4)          // 69632 (two W1 slots)
#define SMEM_K2 (256 * BSTR * 4 + 64)            // 73792

extern "C" void kernel_launch(void* const* d_in, const int* in_sizes, int n_in,
                              void* d_out, int out_size)
{
    const float* x = nullptr;
    const float* nItem = nullptr;
    const float* W1 = nullptr;
    const float* W2 = nullptr;
    for (int k = 0; k < n_in; ++k) {
        switch (in_sizes[k]) {
            case NSET * NSET * MITEM * DIN: x     = (const float*)d_in[k]; break;
            case NSET:                      nItem = (const float*)d_in[k]; break;
            case DIN * NHEAD * DHEAD:       W1    = (const float*)d_in[k]; break;
            case NHEAD:                     W2    = (const float*)d_in[k]; break;
        }
    }

    // Opt-in to >48KB dynamic SMEM. Host-side API, runs before the capture
    // call (static guard); proven graph-safe in rounds 4-6.
    static bool attr_done = false;
    if (!attr_done) {
        cudaFuncSetAttribute(proj_kernel,
                             cudaFuncAttributeMaxDynamicSharedMemorySize, SMEM_K1);
        cudaFuncSetAttribute(score_kernel,
                             cudaFuncAttributeMaxDynamicSharedMemorySize, SMEM_K2);
        attr_done = true;
    }

    prep_w1<<<64, 1024>>>(W1);
    proj_kernel<<<NSET * NSET * 2, 256, SMEM_K1>>>(x);
    score_kernel<<<SCORE_GRID, 256, SMEM_K2>>>(nItem, W2, (float*)d_out);
}

// round 12
// speedup vs baseline: 2.3167x; 1.6345x over previous
#include <cuda_runtime.h>
#include <cuda_fp16.h>
#include <cstdint>

// ---------------------------------------------------------------------------
// cross_set_score (v8): full fp16 pipeline, mma.m16n8k16 (2x tf32 rate,
// same 11-bit significand). Structure identical to v7b:
//  K0: g_W1h = transpose(W1) fp16; zero completion counter
//  K1: proj: CTA = 128 x-rows (reg-resident fp16) x 8 heads; W1 dbl-buffered
//  K2: score: CTA = (pair, head): A reg-resident from gmem, full B in SMEM;
//      fused LeakyReLU+reduce; last CTA finalizes output
// K-pair permutation (sum-invariant, same as verified tf32 path, pair
// granularity): slots {b0,b1} <- k-pairs {2t, 2t+1}; identical for A and B.
// ---------------------------------------------------------------------------

#define NSET  16
#define MITEM 256
#define DIN   128
#define NHEAD 8
#define DHEAD 64
#define NPAIR 136

#define W1STR 72       // words (fp16x2); ==8 mod 32 -> conflict-free LDS.64
#define BSTR  40       // words (fp16x2); ==8 mod 32 -> conflict-free LDS.64

#define SCORE_GRID (NPAIR * NHEAD)

__device__ __half g_H[NSET * NSET * NHEAD * MITEM * DHEAD];  // 67 MB scratch
__device__ __half g_W1h[NHEAD * DHEAD * DIN];                // [head][e][d]
__device__ float  g_scratch[NPAIR * NHEAD];
__device__ int    g_count;

// ---------------- helpers ----------------
__device__ __forceinline__ uint32_t packh2(float a, float b) {
    __half2 h = __floats2half2_rn(a, b);    // .x = a (low), .y = b (high)
    return *(uint32_t*)&h;
}
__device__ __forceinline__ void mma_f16(float* c, const uint32_t* a, const uint32_t* b) {
    asm volatile(
        "mma.sync.aligned.m16n8k16.row.col.f32.f16.f16.f32 "
        "{%0,%1,%2,%3}, {%4,%5,%6,%7}, {%8,%9}, {%0,%1,%2,%3};"
        : "+f"(c[0]), "+f"(c[1]), "+f"(c[2]), "+f"(c[3])
        : "r"(a[0]), "r"(a[1]), "r"(a[2]), "r"(a[3]), "r"(b[0]), "r"(b[1]));
}
__device__ __forceinline__ void cp_async16(uint32_t smem_addr, const void* gptr) {
    asm volatile("cp.async.cg.shared.global [%0], [%1], 16;"
                 :: "r"(smem_addr), "l"(gptr) : "memory");
}
__device__ __forceinline__ void cp_commit() {
    asm volatile("cp.async.commit_group;" ::: "memory");
}
__device__ __forceinline__ void cp_wait0() {
    asm volatile("cp.async.wait_group 0;" ::: "memory");
}
__device__ __forceinline__ uint32_t smem_u32(const void* p) {
    return (uint32_t)__cvta_generic_to_shared(p);
}

// ============================================================================
// Kernel 0: transpose + fp16-round W1; reset completion counter.
// ============================================================================
__global__ void prep_w1(const float* __restrict__ W1)
{
    const int idx = blockIdx.x * 1024 + threadIdx.x;   // 65536 total
    if (idx == 0) g_count = 0;
    const int he  = idx >> 7;            // head*64 + e
    const int d   = idx & 127;
    g_W1h[idx] = __float2half(W1[d * (NHEAD * DHEAD) + he]);
}

// ============================================================================
// Kernel 1: projection. grid = 512 CTAs (256 tiles x 2 halves), 256 thr.
// Warp owns 16 x-rows resident (fp16, 32 regs) across all 8 heads.
// W1 double-buffered via cp.async.
// ============================================================================
__global__ __launch_bounds__(256, 3)
void proj_kernel(const float* __restrict__ x)
{
    extern __shared__ uint32_t w1s[];    // 2 slots of [64][W1STR]

    const int bx   = blockIdx.x;
    const int tile = bx >> 1;
    const int rh   = bx & 1;
    const int tid  = threadIdx.x;
    const int wid  = tid >> 5;
    const int lane = tid & 31;
    const int r    = lane >> 2;          // group id g
    const int c    = lane & 3;           // thread-in-group t
    const uint32_t slot_bytes = DHEAD * W1STR * 4;
    const uint32_t w1s_base   = smem_u32(w1s);

    // stage W1 head h (64 rows x 64 words) into slot s: 1024 uint4, 4/thread
    auto stage_head = [&](int h, int s) {
        const char* src = (const char*)(g_W1h + (size_t)h * DHEAD * DIN);
        const uint32_t dstb = w1s_base + s * slot_bytes;
        #pragma unroll
        for (int it = 0; it < 4; ++it) {
            int idx = tid + it * 256;
            int e = idx >> 4, dq = idx & 15;        // 16 uint4 per row
            cp_async16(dstb + (e * W1STR + dq * 4) * 4, src + idx * 16);
        }
        cp_commit();
    };

    stage_head(0, 0);

    // ---- A resident: 16 rows x 128 K per warp, fp16 (8 k16-steps x 4 regs)
    uint32_t aF[8][4];
    {
        const float* xr0 = x + (size_t)(tile * MITEM + rh * 128 + wid * 16 + r) * DIN;
        const float* xr8 = xr0 + 8 * DIN;
        #pragma unroll
        for (int ks = 0; ks < 8; ++ks) {
            float4 v0 = *(const float4*)(xr0 + ks * 16 + 4 * c);
            float4 v8 = *(const float4*)(xr8 + ks * 16 + 4 * c);
            aF[ks][0] = packh2(v0.x, v0.y);
            aF[ks][2] = packh2(v0.z, v0.w);
            aF[ks][1] = packh2(v8.x, v8.y);
            aF[ks][3] = packh2(v8.z, v8.w);
        }
    }

    cp_wait0();
    __syncthreads();

    #pragma unroll 1
    for (int h = 0; h < NHEAD; ++h) {
        const int s = h & 1;
        if (h < NHEAD - 1) stage_head(h + 1, s ^ 1);

        const uint32_t* w1c = w1s + s * (DHEAD * W1STR);
        __half* Hout = g_H + ((size_t)(tile * NHEAD + h) * MITEM
                              + rh * 128 + wid * 16) * DHEAD;

        #pragma unroll
        for (int ntp = 0; ntp < 4; ++ntp) {
            const int n0 = ntp * 16;
            const int n1 = n0 + 8;
            float acc0[4] = {0.f, 0.f, 0.f, 0.f};
            float acc1[4] = {0.f, 0.f, 0.f, 0.f};
            #pragma unroll
            for (int ks = 0; ks < 8; ++ks) {
                uint2 b0 = *(const uint2*)&w1c[(n0 + r) * W1STR + ks * 8 + 2 * c];
                uint2 b1 = *(const uint2*)&w1c[(n1 + r) * W1STR + ks * 8 + 2 * c];
                mma_f16(acc0, aF[ks], (const uint32_t*)&b0);
                mma_f16(acc1, aF[ks], (const uint32_t*)&b1);
            }
            // store fp16x2: rows r / r+8, cols n0+2c / n1+2c
            *(uint32_t*)&Hout[r * DHEAD + n0 + 2 * c]       = packh2(acc0[0], acc0[1]);
            *(uint32_t*)&Hout[(r + 8) * DHEAD + n0 + 2 * c] = packh2(acc0[2], acc0[3]);
            *(uint32_t*)&Hout[r * DHEAD + n1 + 2 * c]       = packh2(acc1[0], acc1[1]);
            *(uint32_t*)&Hout[(r + 8) * DHEAD + n1 + 2 * c] = packh2(acc1[2], acc1[3]);
        }

        if (h < NHEAD - 1) {
            cp_wait0();
            __syncthreads();
        }
    }
}

// ============================================================================
// Kernel 2: score. grid = 136 pairs * 8 heads = 1088 CTAs, 256 threads.
// Warp tile 32x256: A (2 m-tiles, fp16, 32 regs) resident from gmem,
// full B (256x64 fp16 = 32KB) in SMEM via cp.async. Fused epilogue.
// ============================================================================
__global__ __launch_bounds__(256, 3)
void score_kernel(const float* __restrict__ nItem,
                  const float* __restrict__ W2,
                  float* __restrict__ out)
{
    extern __shared__ uint32_t sm2[];
    uint32_t* Bs   = sm2;                              // [256][BSTR]
    float*    red  = (float*)(sm2 + 256 * BSTR);       // [8]
    int*      flag = (int*)(red + 8);

    const int bx   = blockIdx.x;
    const int pair = bx >> 3;
    const int head = bx & 7;
    const int tid  = threadIdx.x;
    const int wid  = tid >> 5;
    const int lane = tid & 31;
    const int r    = lane >> 2;
    const int c    = lane & 3;

    // pair -> (ii <= jj)
    int q = pair, jj = 0;
    while (q >= jj + 1) { q -= (jj + 1); ++jj; }
    const int ii = q;

    const __half* HA = g_H + (size_t)((jj * NSET + ii) * NHEAD + head) * MITEM * DHEAD;
    const __half* HB = g_H + (size_t)((ii * NSET + jj) * NHEAD + head) * MITEM * DHEAD;

    // ---- kick off B staging (2048 uint4 = 32KB), then load A ----
    {
        const uint32_t bs_base = smem_u32(Bs);
        const char* src = (const char*)HB;
        #pragma unroll
        for (int it = 0; it < 8; ++it) {
            int idx = tid + it * 256;
            int row = idx >> 3, cq = idx & 7;          // 8 uint4 per row
            cp_async16(bs_base + (row * BSTR + cq * 4) * 4, src + idx * 16);
        }
        cp_commit();
    }

    // A resident: 32 rows (2 m-tiles) x 64 K per warp (4 k16-steps x 4 regs)
    uint32_t aF[2][4][4];
    {
        const uint32_t* HAw = (const uint32_t*)HA;     // fp16x2 words, 32/row
        const int wm = wid * 32;
        #pragma unroll
        for (int mt = 0; mt < 2; ++mt) {
            const uint32_t* a0 = HAw + (size_t)(wm + mt * 16 + r) * 32;
            const uint32_t* a8 = a0 + 8 * 32;
            #pragma unroll
            for (int ks = 0; ks < 4; ++ks) {
                uint2 lo = *(const uint2*)(a0 + ks * 8 + 2 * c);
                uint2 hi = *(const uint2*)(a8 + ks * 8 + 2 * c);
                aF[mt][ks][0] = lo.x; aF[mt][ks][2] = lo.y;
                aF[mt][ks][1] = hi.x; aF[mt][ks][3] = hi.y;
            }
        }
    }

    cp_wait0();
    __syncthreads();

    // ---- mainloop: 32 n-tiles, bF shared across both m-tiles ----
    float sum = 0.f;
    #pragma unroll 1
    for (int nt = 0; nt < 32; ++nt) {
        float acc0[4] = {0.f, 0.f, 0.f, 0.f};
        float acc1[4] = {0.f, 0.f, 0.f, 0.f};
        #pragma unroll
        for (int ks = 0; ks < 4; ++ks) {
            uint2 b = *(const uint2*)&Bs[(nt * 8 + r) * BSTR + ks * 8 + 2 * c];
            mma_f16(acc0, aF[0][ks], (const uint32_t*)&b);
            mma_f16(acc1, aF[1][ks], (const uint32_t*)&b);
        }
        #pragma unroll
        for (int e = 0; e < 4; ++e) {
            float v0 = acc0[e], v1 = acc1[e];
            sum += (v0 > 0.f) ? v0 : 0.3f * v0;
            sum += (v1 > 0.f) ? v1 : 0.3f * v1;
        }
    }

    // ---- CTA reduce ----
    #pragma unroll
    for (int off = 16; off; off >>= 1)
        sum += __shfl_xor_sync(0xffffffffu, sum, off);
    if (lane == 0) red[wid] = sum;
    __syncthreads();
    if (tid == 0) {
        float t = 0.f;
        #pragma unroll
        for (int w = 0; w < 8; ++w) t += red[w];
        g_scratch[pair * NHEAD + head] = t;
        __threadfence();
        int done = atomicAdd(&g_count, 1);
        *flag = (done == SCORE_GRID - 1);
    }
    __syncthreads();

    // ---- last CTA: finalize ----
    if (*flag) {
        __threadfence();
        const int t = tid;             // t = j*16 + i
        const int j = t >> 4, i = t & 15;
        const int a = (j > i) ? j : i;
        const int b = (j > i) ? i : j;
        const int p = a * (a + 1) / 2 + b;
        float s = 0.f;
        #pragma unroll
        for (int hh = 0; hh < NHEAD; ++hh)
            s += g_scratch[p * NHEAD + hh] * W2[hh];
        out[t] = s / (8.0f * nItem[i] * nItem[j]);   // 8 = sqrt(D=64)
    }
}

// ---------------- entry point ----------------
#define SMEM_K1 (2 * DHEAD * W1STR * 4)          // 36864
#define SMEM_K2 (256 * BSTR * 4 + 64)            // 41024

extern "C" void kernel_launch(void* const* d_in, const int* in_sizes, int n_in,
                              void* d_out, int out_size)
{
    const float* x = nullptr;
    const float* nItem = nullptr;
    const float* W1 = nullptr;
    const float* W2 = nullptr;
    for (int k = 0; k < n_in; ++k) {
        switch (in_sizes[k]) {
            case NSET * NSET * MITEM * DIN: x     = (const float*)d_in[k]; break;
            case NSET:                      nItem = (const float*)d_in[k]; break;
            case DIN * NHEAD * DHEAD:       W1    = (const float*)d_in[k]; break;
            case NHEAD:                     W2    = (const float*)d_in[k]; break;
        }
    }

    static bool attr_done = false;
    if (!attr_done) {
        cudaFuncSetAttribute(proj_kernel,
                             cudaFuncAttributeMaxDynamicSharedMemorySize, SMEM_K1);
        cudaFuncSetAttribute(score_kernel,
                             cudaFuncAttributeMaxDynamicSharedMemorySize, SMEM_K2);
        attr_done = true;
    }

    prep_w1<<<64, 1024>>>(W1);
    proj_kernel<<<NSET * NSET * 2, 256, SMEM_K1>>>(x);
    score_kernel<<<SCORE_GRID, 256, SMEM_K2>>>(nItem, W2, (float*)d_out);
}

// round 13
// speedup vs baseline: 2.5628x; 1.1062x over previous
#include <cuda_runtime.h>
#include <cuda_fp16.h>
#include <cstdint>

// ---------------------------------------------------------------------------
// cross_set_score (v9): v8 + branch-free LeakyReLU (0.65v + 0.35|v| dual
// accumulators) + packed STG.64 H stores (consistent K-permutation).
//  K0: g_W1h = transpose(W1) fp16; zero completion counter
//  K1: proj: CTA = 128 x-rows (reg-resident fp16) x 8 heads; W1 dbl-buffered
//  K2: score: CTA = (pair, head): A reg-resident from gmem, full B in SMEM;
//      fused reduce; last CTA finalizes output
// H physical layout is a fixed permutation of logical K columns; score reads
// A and B fragments with the identical word formula, so mma pairing is
// consistent (sum over K is permutation-invariant).
// ---------------------------------------------------------------------------

#define NSET  16
#define MITEM 256
#define DIN   128
#define NHEAD 8
#define DHEAD 64
#define NPAIR 136

#define W1STR 72       // words (fp16x2); ==8 mod 32 -> conflict-free LDS.64
#define BSTR  40       // words (fp16x2); ==8 mod 32 -> conflict-free LDS.64

#define SCORE_GRID (NPAIR * NHEAD)

__device__ __half g_H[NSET * NSET * NHEAD * MITEM * DHEAD];  // 67 MB scratch
__device__ __half g_W1h[NHEAD * DHEAD * DIN];                // [head][e][d]
__device__ float  g_scratch[NPAIR * NHEAD];
__device__ int    g_count;

// ---------------- helpers ----------------
__device__ __forceinline__ uint32_t packh2(float a, float b) {
    __half2 h = __floats2half2_rn(a, b);
    return *(uint32_t*)&h;
}
__device__ __forceinline__ void mma_f16(float* c, const uint32_t* a, const uint32_t* b) {
    asm volatile(
        "mma.sync.aligned.m16n8k16.row.col.f32.f16.f16.f32 "
        "{%0,%1,%2,%3}, {%4,%5,%6,%7}, {%8,%9}, {%0,%1,%2,%3};"
        : "+f"(c[0]), "+f"(c[1]), "+f"(c[2]), "+f"(c[3])
        : "r"(a[0]), "r"(a[1]), "r"(a[2]), "r"(a[3]), "r"(b[0]), "r"(b[1]));
}
__device__ __forceinline__ void cp_async16(uint32_t smem_addr, const void* gptr) {
    asm volatile("cp.async.cg.shared.global [%0], [%1], 16;"
                 :: "r"(smem_addr), "l"(gptr) : "memory");
}
__device__ __forceinline__ void cp_commit() {
    asm volatile("cp.async.commit_group;" ::: "memory");
}
__device__ __forceinline__ void cp_wait0() {
    asm volatile("cp.async.wait_group 0;" ::: "memory");
}
__device__ __forceinline__ uint32_t smem_u32(const void* p) {
    return (uint32_t)__cvta_generic_to_shared(p);
}

// ============================================================================
// Kernel 0: transpose + fp16-round W1; reset completion counter.
// ============================================================================
__global__ void prep_w1(const float* __restrict__ W1)
{
    const int idx = blockIdx.x * 1024 + threadIdx.x;   // 65536 total
    if (idx == 0) g_count = 0;
    const int he  = idx >> 7;            // head*64 + e
    const int d   = idx & 127;
    g_W1h[idx] = __float2half(W1[d * (NHEAD * DHEAD) + he]);
}

// ============================================================================
// Kernel 1: projection. grid = 512 CTAs (256 tiles x 2 halves), 256 thr.
// Warp owns 16 x-rows resident (fp16, 32 regs) across all 8 heads.
// W1 double-buffered via cp.async. H stored as packed uint2 (STG.64).
// ============================================================================
__global__ __launch_bounds__(256, 3)
void proj_kernel(const float* __restrict__ x)
{
    extern __shared__ uint32_t w1s[];    // 2 slots of [64][W1STR]

    const int bx   = blockIdx.x;
    const int tile = bx >> 1;
    const int rh   = bx & 1;
    const int tid  = threadIdx.x;
    const int wid  = tid >> 5;
    const int lane = tid & 31;
    const int r    = lane >> 2;
    const int c    = lane & 3;
    const uint32_t slot_bytes = DHEAD * W1STR * 4;
    const uint32_t w1s_base   = smem_u32(w1s);

    auto stage_head = [&](int h, int s) {
        const char* src = (const char*)(g_W1h + (size_t)h * DHEAD * DIN);
        const uint32_t dstb = w1s_base + s * slot_bytes;
        #pragma unroll
        for (int it = 0; it < 4; ++it) {
            int idx = tid + it * 256;
            int e = idx >> 4, dq = idx & 15;
            cp_async16(dstb + (e * W1STR + dq * 4) * 4, src + idx * 16);
        }
        cp_commit();
    };

    stage_head(0, 0);

    // ---- A resident: 16 rows x 128 K per warp, fp16 (8 k16-steps x 4 regs)
    uint32_t aF[8][4];
    {
        const float* xr0 = x + (size_t)(tile * MITEM + rh * 128 + wid * 16 + r) * DIN;
        const float* xr8 = xr0 + 8 * DIN;
        #pragma unroll
        for (int ks = 0; ks < 8; ++ks) {
            float4 v0 = *(const float4*)(xr0 + ks * 16 + 4 * c);
            float4 v8 = *(const float4*)(xr8 + ks * 16 + 4 * c);
            aF[ks][0] = packh2(v0.x, v0.y);
            aF[ks][2] = packh2(v0.z, v0.w);
            aF[ks][1] = packh2(v8.x, v8.y);
            aF[ks][3] = packh2(v8.z, v8.w);
        }
    }

    cp_wait0();
    __syncthreads();

    #pragma unroll 1
    for (int h = 0; h < NHEAD; ++h) {
        const int s = h & 1;
        if (h < NHEAD - 1) stage_head(h + 1, s ^ 1);

        const uint32_t* w1c = w1s + s * (DHEAD * W1STR);
        // H row = 16 uint2; this warp's rows start at wid*16
        uint2* Hw = (uint2*)(g_H + ((size_t)(tile * NHEAD + h) * MITEM
                                    + rh * 128 + wid * 16) * DHEAD);

        #pragma unroll
        for (int ntp = 0; ntp < 4; ++ntp) {
            const int n0 = ntp * 16;
            const int n1 = n0 + 8;
            float acc0[4] = {0.f, 0.f, 0.f, 0.f};
            float acc1[4] = {0.f, 0.f, 0.f, 0.f};
            #pragma unroll
            for (int ks = 0; ks < 8; ++ks) {
                uint2 b0 = *(const uint2*)&w1c[(n0 + r) * W1STR + ks * 8 + 2 * c];
                uint2 b1 = *(const uint2*)&w1c[(n1 + r) * W1STR + ks * 8 + 2 * c];
                mma_f16(acc0, aF[ks], (const uint32_t*)&b0);
                mma_f16(acc1, aF[ks], (const uint32_t*)&b1);
            }
            // packed store: physical uint2 index = row*16 + ntp*4 + c
            // logical cols (n0+2c, n0+2c+1, n1+2c, n1+2c+1) -- fixed K-perm,
            // consistent with score's identical A/B read formula.
            uint2 lo = { packh2(acc0[0], acc0[1]), packh2(acc1[0], acc1[1]) };
            uint2 hi = { packh2(acc0[2], acc0[3]), packh2(acc1[2], acc1[3]) };
            Hw[(size_t)r * 16 + ntp * 4 + c]       = lo;
            Hw[(size_t)(r + 8) * 16 + ntp * 4 + c] = hi;
        }

        if (h < NHEAD - 1) {
            cp_wait0();
            __syncthreads();
        }
    }
}

// ============================================================================
// Kernel 2: score. grid = 136 pairs * 8 heads = 1088 CTAs, 256 threads.
// Warp tile 32x256: A (2 m-tiles, fp16) resident from gmem, full B in SMEM.
// Branch-free LeakyReLU: s1 += v, s2 += |v|; total = 0.65*s1 + 0.35*s2.
// ============================================================================
__global__ __launch_bounds__(256, 3)
void score_kernel(const float* __restrict__ nItem,
                  const float* __restrict__ W2,
                  float* __restrict__ out)
{
    extern __shared__ uint32_t sm2[];
    uint32_t* Bs   = sm2;                              // [256][BSTR]
    float*    red  = (float*)(sm2 + 256 * BSTR);       // [8]
    int*      flag = (int*)(red + 8);

    const int bx   = blockIdx.x;
    const int pair = bx >> 3;
    const int head = bx & 7;
    const int tid  = threadIdx.x;
    const int wid  = tid >> 5;
    const int lane = tid & 31;
    const int r    = lane >> 2;
    const int c    = lane & 3;

    // pair -> (ii <= jj)
    int q = pair, jj = 0;
    while (q >= jj + 1) { q -= (jj + 1); ++jj; }
    const int ii = q;

    const __half* HA = g_H + (size_t)((jj * NSET + ii) * NHEAD + head) * MITEM * DHEAD;
    const __half* HB = g_H + (size_t)((ii * NSET + jj) * NHEAD + head) * MITEM * DHEAD;

    // ---- kick off B staging (2048 uint4 = 32KB), then load A ----
    {
        const uint32_t bs_base = smem_u32(Bs);
        const char* src = (const char*)HB;
        #pragma unroll
        for (int it = 0; it < 8; ++it) {
            int idx = tid + it * 256;
            int row = idx >> 3, cq = idx & 7;          // 8 uint4 per row
            cp_async16(bs_base + (row * BSTR + cq * 4) * 4, src + idx * 16);
        }
        cp_commit();
    }

    // A resident: 32 rows (2 m-tiles) x 64 K per warp (4 k16-steps x 4 regs)
    uint32_t aF[2][4][4];
    {
        const uint32_t* HAw = (const uint32_t*)HA;     // fp16x2 words, 32/row
        const int wm = wid * 32;
        #pragma unroll
        for (int mt = 0; mt < 2; ++mt) {
            const uint32_t* a0 = HAw + (size_t)(wm + mt * 16 + r) * 32;
            const uint32_t* a8 = a0 + 8 * 32;
            #pragma unroll
            for (int ks = 0; ks < 4; ++ks) {
                uint2 lo = *(const uint2*)(a0 + ks * 8 + 2 * c);
                uint2 hi = *(const uint2*)(a8 + ks * 8 + 2 * c);
                aF[mt][ks][0] = lo.x; aF[mt][ks][2] = lo.y;
                aF[mt][ks][1] = hi.x; aF[mt][ks][3] = hi.y;
            }
        }
    }

    cp_wait0();
    __syncthreads();

    // ---- mainloop: 32 n-tiles; dual accumulators (branch-free leaky) ----
    float s1 = 0.f, s2 = 0.f;
    #pragma unroll 1
    for (int nt = 0; nt < 32; ++nt) {
        float acc0[4] = {0.f, 0.f, 0.f, 0.f};
        float acc1[4] = {0.f, 0.f, 0.f, 0.f};
        #pragma unroll
        for (int ks = 0; ks < 4; ++ks) {
            uint2 b = *(const uint2*)&Bs[(nt * 8 + r) * BSTR + ks * 8 + 2 * c];
            mma_f16(acc0, aF[0][ks], (const uint32_t*)&b);
            mma_f16(acc1, aF[1][ks], (const uint32_t*)&b);
        }
        #pragma unroll
        for (int e = 0; e < 4; ++e) {
            s1 += acc0[e];          s2 += fabsf(acc0[e]);
            s1 += acc1[e];          s2 += fabsf(acc1[e]);
        }
    }
    float sum = 0.65f * s1 + 0.35f * s2;   // == sum of leaky(v), alpha=0.3

    // ---- CTA reduce ----
    #pragma unroll
    for (int off = 16; off; off >>= 1)
        sum += __shfl_xor_sync(0xffffffffu, sum, off);
    if (lane == 0) red[wid] = sum;
    __syncthreads();
    if (tid == 0) {
        float t = 0.f;
        #pragma unroll
        for (int w = 0; w < 8; ++w) t += red[w];
        g_scratch[pair * NHEAD + head] = t;
        __threadfence();
        int done = atomicAdd(&g_count, 1);
        *flag = (done == SCORE_GRID - 1);
    }
    __syncthreads();

    // ---- last CTA: finalize ----
    if (*flag) {
        __threadfence();
        const int t = tid;             // t = j*16 + i
        const int j = t >> 4, i = t & 15;
        const int a = (j > i) ? j : i;
        const int b = (j > i) ? i : j;
        const int p = a * (a + 1) / 2 + b;
        float s = 0.f;
        #pragma unroll
        for (int hh = 0; hh < NHEAD; ++hh)
            s += g_scratch[p * NHEAD + hh] * W2[hh];
        out[t] = s / (8.0f * nItem[i] * nItem[j]);   // 8 = sqrt(D=64)
    }
}

// ---------------- entry point ----------------
#define SMEM_K1 (2 * DHEAD * W1STR * 4)          // 36864
#define SMEM_K2 (256 * BSTR * 4 + 64)            // 41024

extern "C" void kernel_launch(void* const* d_in, const int* in_sizes, int n_in,
                              void* d_out, int out_size)
{
    const float* x = nullptr;
    const float* nItem = nullptr;
    const float* W1 = nullptr;
    const float* W2 = nullptr;
    for (int k = 0; k < n_in; ++k) {
        switch (in_sizes[k]) {
            case NSET * NSET * MITEM * DIN: x     = (const float*)d_in[k]; break;
            case NSET:                      nItem = (const float*)d_in[k]; break;
            case DIN * NHEAD * DHEAD:       W1    = (const float*)d_in[k]; break;
            case NHEAD:                     W2    = (const float*)d_in[k]; break;
        }
    }

    static bool attr_done = false;
    if (!attr_done) {
        cudaFuncSetAttribute(proj_kernel,
                             cudaFuncAttributeMaxDynamicSharedMemorySize, SMEM_K1);
        cudaFuncSetAttribute(score_kernel,
                             cudaFuncAttributeMaxDynamicSharedMemorySize, SMEM_K2);
        attr_done = true;
    }

    prep_w1<<<64, 1024>>>(W1);
    proj_kernel<<<NSET * NSET * 2, 256, SMEM_K1>>>(x);
    score_kernel<<<SCORE_GRID, 256, SMEM_K2>>>(nItem, W2, (float*)d_out);
}